// round 1
// baseline (speedup 1.0000x reference)
#include <cuda_runtime.h>
#include <cuda_bf16.h>
#include <cstdint>

#define BATCH 16
#define CHAN  64
#define NPTS  65536
#define RXr   32
#define RES   (32*32*32)   // 32768

// ---------------- scratch (device globals; no allocations allowed) ----------
__device__ float        g_meansum[BATCH * 3];
__device__ unsigned int g_maxnorm[BATCH];          // float bits of max squared norm
__device__ int          g_voxidx[BATCH * NPTS];    // flat voxel index per point
__device__ int          g_counts[BATCH * RES];     // points per voxel
__device__ float        g_pinv[BATCH * NPTS];      // 1/max(cnt,1) gathered per point

// ---------------- kernel 0: zero scratch ------------------------------------
__global__ void zero_scratch_kernel() {
    int i = blockIdx.x * blockDim.x + threadIdx.x;
    int total = BATCH * RES;
    if (i < total) g_counts[i] = 0;
    if (i < BATCH * 3) g_meansum[i] = 0.0f;
    if (i < BATCH) g_maxnorm[i] = 0u;
}

// ---------------- kernel 1: per-batch coordinate mean (sum) ------------------
__global__ void mean_kernel(const float* __restrict__ coords) {
    int b = blockIdx.y;
    const float* cb = coords + (size_t)b * 3 * NPTS;
    float sx = 0.f, sy = 0.f, sz = 0.f;
    for (int n = blockIdx.x * blockDim.x + threadIdx.x; n < NPTS;
         n += gridDim.x * blockDim.x) {
        sx += cb[n];
        sy += cb[NPTS + n];
        sz += cb[2 * NPTS + n];
    }
    // warp reduce
    for (int o = 16; o > 0; o >>= 1) {
        sx += __shfl_down_sync(0xffffffffu, sx, o);
        sy += __shfl_down_sync(0xffffffffu, sy, o);
        sz += __shfl_down_sync(0xffffffffu, sz, o);
    }
    __shared__ float shx[8], shy[8], shz[8];
    int warp = threadIdx.x >> 5, lane = threadIdx.x & 31;
    if (lane == 0) { shx[warp] = sx; shy[warp] = sy; shz[warp] = sz; }
    __syncthreads();
    if (threadIdx.x == 0) {
        float tx = 0.f, ty = 0.f, tz = 0.f;
        int nw = blockDim.x >> 5;
        for (int w = 0; w < nw; w++) { tx += shx[w]; ty += shy[w]; tz += shz[w]; }
        atomicAdd(&g_meansum[b * 3 + 0], tx);
        atomicAdd(&g_meansum[b * 3 + 1], ty);
        atomicAdd(&g_meansum[b * 3 + 2], tz);
    }
}

// ---------------- kernel 2: per-batch max squared norm of centered coords ----
__global__ void maxnorm_kernel(const float* __restrict__ coords) {
    int b = blockIdx.y;
    const float* cb = coords + (size_t)b * 3 * NPTS;
    const float inv_n = 1.0f / (float)NPTS;
    float mx = g_meansum[b * 3 + 0] * inv_n;
    float my = g_meansum[b * 3 + 1] * inv_n;
    float mz = g_meansum[b * 3 + 2] * inv_n;
    float best = 0.f;
    for (int n = blockIdx.x * blockDim.x + threadIdx.x; n < NPTS;
         n += gridDim.x * blockDim.x) {
        float dx = cb[n] - mx;
        float dy = cb[NPTS + n] - my;
        float dz = cb[2 * NPTS + n] - mz;
        float n2 = dx * dx + dy * dy + dz * dz;
        best = fmaxf(best, n2);
    }
    for (int o = 16; o > 0; o >>= 1)
        best = fmaxf(best, __shfl_down_sync(0xffffffffu, best, o));
    __shared__ float sh[8];
    int warp = threadIdx.x >> 5, lane = threadIdx.x & 31;
    if (lane == 0) sh[warp] = best;
    __syncthreads();
    if (threadIdx.x == 0) {
        float t = 0.f;
        int nw = blockDim.x >> 5;
        for (int w = 0; w < nw; w++) t = fmaxf(t, sh[w]);
        atomicMax(&g_maxnorm[b], __float_as_uint(t)); // nonneg floats: uint order ok
    }
}

// ---------------- kernel 3: per-point normalize, write norm_coords, count ----
__global__ void point_kernel(const float* __restrict__ coords,
                             float* __restrict__ norm_out) {
    int b = blockIdx.y;
    const float* cb = coords + (size_t)b * 3 * NPTS;
    float* nb = norm_out + (size_t)b * 3 * NPTS;
    const float inv_n = 1.0f / (float)NPTS;
    float mx = g_meansum[b * 3 + 0] * inv_n;
    float my = g_meansum[b * 3 + 1] * inv_n;
    float mz = g_meansum[b * 3 + 2] * inv_n;
    float denom = sqrtf(__uint_as_float(g_maxnorm[b])) * 2.0f;
    float inv_d = 1.0f / denom;

    for (int n = blockIdx.x * blockDim.x + threadIdx.x; n < NPTS;
         n += gridDim.x * blockDim.x) {
        float sx = ((cb[n]            - mx) * inv_d + 0.5f) * (float)RXr;
        float sy = ((cb[NPTS + n]     - my) * inv_d + 0.5f) * (float)RXr;
        float sz = ((cb[2 * NPTS + n] - mz) * inv_d + 0.5f) * (float)RXr;
        sx = fminf(fmaxf(sx, 0.0f), 31.0f);
        sy = fminf(fmaxf(sy, 0.0f), 31.0f);
        sz = fminf(fmaxf(sz, 0.0f), 31.0f);
        nb[n]            = sx;
        nb[NPTS + n]     = sy;
        nb[2 * NPTS + n] = sz;
        int vx = (int)rintf(sx);   // rintf = round-half-even, matches jnp.round
        int vy = (int)rintf(sy);
        int vz = (int)rintf(sz);
        int idx = vx * (32 * 32) + vy * 32 + vz;
        g_voxidx[b * NPTS + n] = idx;
        atomicAdd(&g_counts[b * RES + idx], 1);
    }
}

// ---------------- kernel 4: per-point inverse count --------------------------
__global__ void pinv_kernel() {
    int p = blockIdx.x * blockDim.x + threadIdx.x;
    if (p >= BATCH * NPTS) return;
    int b = p >> 16;               // NPTS == 65536
    int idx = g_voxidx[p];
    int c = g_counts[b * RES + idx];
    g_pinv[p] = 1.0f / (float)max(c, 1);
}

// ---------------- kernel 5: scatter-add features * pinv ----------------------
__global__ void scatter_kernel(const float* __restrict__ features,
                               float* __restrict__ out) {
    // each thread handles 4 consecutive points of one (b, c) row
    int t = blockIdx.x * blockDim.x + threadIdx.x;
    size_t i = (size_t)t * 4;                        // element index into [B,C,N]
    int n  = (int)(i & (NPTS - 1));
    int bc = (int)(i >> 16);                         // N = 2^16
    int c  = bc & (CHAN - 1);
    int b  = bc >> 6;

    const float4 f4 = *reinterpret_cast<const float4*>(features + i);
    const int4   v4 = *reinterpret_cast<const int4*>(&g_voxidx[b * NPTS + n]);
    const float4 p4 = *reinterpret_cast<const float4*>(&g_pinv[b * NPTS + n]);

    float* base = out + ((size_t)b * CHAN + c) * RES;
    atomicAdd(base + v4.x, f4.x * p4.x);
    atomicAdd(base + v4.y, f4.y * p4.y);
    atomicAdd(base + v4.z, f4.z * p4.z);
    atomicAdd(base + v4.w, f4.w * p4.w);
}

// ---------------- launcher ---------------------------------------------------
extern "C" void kernel_launch(void* const* d_in, const int* in_sizes, int n_in,
                              void* d_out, int out_size) {
    const float* features = (const float*)d_in[0];  // [B, C, N]
    const float* coords   = (const float*)d_in[1];  // [B, 3, N]
    float* out = (float*)d_out;                     // [B,C,32,32,32] then [B,3,N]
    float* norm_out = out + (size_t)BATCH * CHAN * RES;

    // zero the averaged-feature region (atomics accumulate into it)
    cudaMemsetAsync(d_out, 0, (size_t)BATCH * CHAN * RES * sizeof(float), 0);

    {   // zero scratch
        int total = BATCH * RES;
        zero_scratch_kernel<<<(total + 255) / 256, 256>>>();
    }

    dim3 grid_b(32, BATCH);
    mean_kernel<<<grid_b, 256>>>(coords);
    maxnorm_kernel<<<grid_b, 256>>>(coords);
    point_kernel<<<grid_b, 256>>>(coords, norm_out);

    pinv_kernel<<<(BATCH * NPTS + 255) / 256, 256>>>();

    {   // 67,108,864 elements / 4 per thread = 16,777,216 threads
        int threads = 256;
        int blocks = (BATCH * CHAN * NPTS / 4) / threads;
        scatter_kernel<<<blocks, threads>>>(features, out);
    }
}

// round 3
// speedup vs baseline: 1.9449x; 1.9449x over previous
#include <cuda_runtime.h>
#include <cuda_bf16.h>
#include <cstdint>

#define BATCH 16
#define CHAN  64
#define NPTS  65536
#define RES   (32*32*32)   // 32768

// ---------------- scratch (device globals; no allocations allowed) ----------
__device__ float        g_meansum[BATCH * 3];
__device__ unsigned int g_maxnorm[BATCH];          // float bits of max squared norm
__device__ int          g_voxidx[BATCH * NPTS];    // flat voxel index per point
__device__ int          g_counts[BATCH * RES];     // points per voxel
__device__ float        g_accum[(size_t)BATCH * RES * CHAN]; // [B, RES, C] sums

// ---------------- kernel 0: zero all scratch ---------------------------------
__global__ void zero_kernel() {
    int i = blockIdx.x * blockDim.x + threadIdx.x;   // 8,388,608 threads
    float4 z = make_float4(0.f, 0.f, 0.f, 0.f);
    reinterpret_cast<float4*>(g_accum)[i] = z;       // 33.5M floats / 4
    if (i < BATCH * RES / 4)
        reinterpret_cast<int4*>(g_counts)[i] = make_int4(0, 0, 0, 0);
    if (i < BATCH * 3) g_meansum[i] = 0.0f;
    if (i < BATCH)     g_maxnorm[i] = 0u;
}

// ---------------- kernel 1: per-batch coordinate mean (sum) ------------------
__global__ void mean_kernel(const float* __restrict__ coords) {
    int b = blockIdx.y;
    const float* cb = coords + (size_t)b * 3 * NPTS;
    float sx = 0.f, sy = 0.f, sz = 0.f;
    for (int n = blockIdx.x * blockDim.x + threadIdx.x; n < NPTS;
         n += gridDim.x * blockDim.x) {
        sx += cb[n];
        sy += cb[NPTS + n];
        sz += cb[2 * NPTS + n];
    }
    for (int o = 16; o > 0; o >>= 1) {
        sx += __shfl_down_sync(0xffffffffu, sx, o);
        sy += __shfl_down_sync(0xffffffffu, sy, o);
        sz += __shfl_down_sync(0xffffffffu, sz, o);
    }
    __shared__ float shx[8], shy[8], shz[8];
    int warp = threadIdx.x >> 5, lane = threadIdx.x & 31;
    if (lane == 0) { shx[warp] = sx; shy[warp] = sy; shz[warp] = sz; }
    __syncthreads();
    if (threadIdx.x == 0) {
        float tx = 0.f, ty = 0.f, tz = 0.f;
        int nw = blockDim.x >> 5;
        for (int w = 0; w < nw; w++) { tx += shx[w]; ty += shy[w]; tz += shz[w]; }
        atomicAdd(&g_meansum[b * 3 + 0], tx);
        atomicAdd(&g_meansum[b * 3 + 1], ty);
        atomicAdd(&g_meansum[b * 3 + 2], tz);
    }
}

// ---------------- kernel 2: per-batch max squared norm of centered coords ----
__global__ void maxnorm_kernel(const float* __restrict__ coords) {
    int b = blockIdx.y;
    const float* cb = coords + (size_t)b * 3 * NPTS;
    const float inv_n = 1.0f / (float)NPTS;
    float mx = g_meansum[b * 3 + 0] * inv_n;
    float my = g_meansum[b * 3 + 1] * inv_n;
    float mz = g_meansum[b * 3 + 2] * inv_n;
    float best = 0.f;
    for (int n = blockIdx.x * blockDim.x + threadIdx.x; n < NPTS;
         n += gridDim.x * blockDim.x) {
        float dx = cb[n] - mx;
        float dy = cb[NPTS + n] - my;
        float dz = cb[2 * NPTS + n] - mz;
        best = fmaxf(best, dx * dx + dy * dy + dz * dz);
    }
    for (int o = 16; o > 0; o >>= 1)
        best = fmaxf(best, __shfl_down_sync(0xffffffffu, best, o));
    __shared__ float sh[8];
    int warp = threadIdx.x >> 5, lane = threadIdx.x & 31;
    if (lane == 0) sh[warp] = best;
    __syncthreads();
    if (threadIdx.x == 0) {
        float t = 0.f;
        int nw = blockDim.x >> 5;
        for (int w = 0; w < nw; w++) t = fmaxf(t, sh[w]);
        atomicMax(&g_maxnorm[b], __float_as_uint(t)); // nonneg floats: uint order ok
    }
}

// ---------------- kernel 3: per-point normalize, write norm_coords, count ----
__global__ void point_kernel(const float* __restrict__ coords,
                             float* __restrict__ norm_out) {
    int b = blockIdx.y;
    const float* cb = coords + (size_t)b * 3 * NPTS;
    float* nb = norm_out + (size_t)b * 3 * NPTS;
    const float inv_n = 1.0f / (float)NPTS;
    float mx = g_meansum[b * 3 + 0] * inv_n;
    float my = g_meansum[b * 3 + 1] * inv_n;
    float mz = g_meansum[b * 3 + 2] * inv_n;
    float inv_d = 1.0f / (sqrtf(__uint_as_float(g_maxnorm[b])) * 2.0f);

    for (int n = blockIdx.x * blockDim.x + threadIdx.x; n < NPTS;
         n += gridDim.x * blockDim.x) {
        float sx = ((cb[n]            - mx) * inv_d + 0.5f) * 32.0f;
        float sy = ((cb[NPTS + n]     - my) * inv_d + 0.5f) * 32.0f;
        float sz = ((cb[2 * NPTS + n] - mz) * inv_d + 0.5f) * 32.0f;
        sx = fminf(fmaxf(sx, 0.0f), 31.0f);
        sy = fminf(fmaxf(sy, 0.0f), 31.0f);
        sz = fminf(fmaxf(sz, 0.0f), 31.0f);
        nb[n]            = sx;
        nb[NPTS + n]     = sy;
        nb[2 * NPTS + n] = sz;
        int vx = (int)rintf(sx);   // round-half-even, matches jnp.round
        int vy = (int)rintf(sy);
        int vz = (int)rintf(sz);
        int idx = (vx << 10) + (vy << 5) + vz;
        g_voxidx[(b << 16) + n] = idx;
        atomicAdd(&g_counts[b * RES + idx], 1);
    }
}

// ---------------- kernel 4: scatter with v4 vector atomics -------------------
// thread = (b, 4-channel group cg, point n). Warp lanes share (b,cg), have
// consecutive n -> 4 coalesced 128B feature loads. One red.global.add.v4.f32
// into channel-contiguous scratch [B, RES, 64].
__global__ void scatter_kernel(const float* __restrict__ features) {
    int tid = blockIdx.x * blockDim.x + threadIdx.x;  // 16,777,216 threads
    int n  = tid & (NPTS - 1);
    int g  = tid >> 16;            // b*16 + cg
    int cg = g & 15;
    int b  = g >> 4;

    const float* f = features + ((size_t)(b * CHAN + cg * 4)) * NPTS + n;
    float f0 = f[0];
    float f1 = f[NPTS];
    float f2 = f[2 * NPTS];
    float f3 = f[3 * NPTS];

    int v = g_voxidx[(b << 16) + n];
    float* dst = g_accum + (((size_t)(b * RES + v)) << 6) + (cg << 2);
    asm volatile("red.global.add.v4.f32 [%0], {%1, %2, %3, %4};"
                 :: "l"(dst), "f"(f0), "f"(f1), "f"(f2), "f"(f3)
                 : "memory");
}

// ---------------- kernel 5: transpose [B,RES,C] -> [B,C,RES] with divide -----
__global__ void transpose_kernel(float* __restrict__ out) {
    // block = (b, 32-voxel chunk); 256 threads; smem tile [32][65]
    __shared__ float tile[32][65];
    __shared__ float inv[32];
    int chunk = blockIdx.x;        // 0 .. B*RES/32-1
    int b  = chunk >> 10;          // RES/32 = 1024 chunks per batch
    int v0 = (chunk & 1023) << 5;

    const float* src = g_accum + (((size_t)(b * RES + v0)) << 6);
    #pragma unroll
    for (int k = 0; k < 8; k++) {
        int idx = threadIdx.x + (k << 8);   // 0..2047
        int c  = idx & 63;
        int vl = idx >> 6;
        tile[vl][c] = src[(size_t)(vl << 6) + c];
    }
    if (threadIdx.x < 32) {
        int c = g_counts[b * RES + v0 + threadIdx.x];
        inv[threadIdx.x] = 1.0f / (float)max(c, 1);
    }
    __syncthreads();

    int lane = threadIdx.x & 31;
    int wrp  = threadIdx.x >> 5;
    #pragma unroll
    for (int k = 0; k < 8; k++) {
        int c = wrp + (k << 3);            // 0..63
        out[((size_t)(b * CHAN + c)) * RES + v0 + lane] = tile[lane][c] * inv[lane];
    }
}

// ---------------- launcher ---------------------------------------------------
extern "C" void kernel_launch(void* const* d_in, const int* in_sizes, int n_in,
                              void* d_out, int out_size) {
    const float* features = (const float*)d_in[0];  // [B, C, N]
    const float* coords   = (const float*)d_in[1];  // [B, 3, N]
    float* out = (float*)d_out;                     // [B,C,32,32,32] ++ [B,3,N]
    float* norm_out = out + (size_t)BATCH * CHAN * RES;

    zero_kernel<<<32768, 256>>>();                  // 8.4M threads, float4 stores

    dim3 grid_b(32, BATCH);
    mean_kernel<<<grid_b, 256>>>(coords);
    maxnorm_kernel<<<grid_b, 256>>>(coords);
    point_kernel<<<grid_b, 256>>>(coords, norm_out);

    scatter_kernel<<<65536, 256>>>(features);       // 16.8M threads, v4 reds

    transpose_kernel<<<BATCH * RES / 32, 256>>>(out);
}